// round 15
// baseline (speedup 1.0000x reference)
#include <cuda_runtime.h>
#include <cuda_fp16.h>
#include <math.h>
#include <stdint.h>

#define B_N 32768
#define C_N 1024
#define H_N 1024
#define S_N 8
#define DC_N 64
#define PERM_N (B_N + S_N * 32)   // 33024 = 256*129

// device-global scratch (allocation-free per harness rules)
__device__ __half g_hid[(size_t)B_N * H_N];     // hidden (half) between GEMM1/GEMM2
__device__ __half g_wt1[(size_t)H_N * C_N];     // Wa1[:C,:]^T half  [n][k]
__device__ __half g_wt2[(size_t)C_N * H_N];     // Wa2^T half  [n][k]
__device__ __half g_wc1h[(size_t)S_N * DC_N * C_N]; // Wc1^T half [s][d][k]
__device__ float  g_embc[S_N * H_N];            // emb[s] @ Wa1[C:,:] + ba1
__device__ int    g_perm[PERM_N];

// ---------------------------------------------------------------------------
// helpers
// ---------------------------------------------------------------------------
__device__ __forceinline__ uint32_t smem_u32(const void* p) {
    uint32_t a;
    asm("{ .reg .u64 t; cvta.to.shared.u64 t, %1; cvt.u32.u64 %0, t; }" : "=r"(a) : "l"(p));
    return a;
}

#define LDSM4(R0, R1, R2, R3, ADDR) \
    asm volatile("ldmatrix.sync.aligned.m8n8.x4.shared.b16 {%0,%1,%2,%3}, [%4];" \
                 : "=r"(R0), "=r"(R1), "=r"(R2), "=r"(R3) : "r"(ADDR))

#define LDSM2(R0, R1, ADDR) \
    asm volatile("ldmatrix.sync.aligned.m8n8.x2.shared.b16 {%0,%1}, [%2];" \
                 : "=r"(R0), "=r"(R1) : "r"(ADDR))

#define MMA16816(C, A, B0, B1) \
    asm volatile("mma.sync.aligned.m16n8k16.row.col.f32.f16.f16.f32 " \
                 "{%0,%1,%2,%3},{%4,%5,%6,%7},{%8,%9},{%0,%1,%2,%3};" \
                 : "+f"((C)[0]), "+f"((C)[1]), "+f"((C)[2]), "+f"((C)[3]) \
                 : "r"((A)[0]), "r"((A)[1]), "r"((A)[2]), "r"((A)[3]), \
                   "r"(B0), "r"(B1))

#define CPA16(DST, SRC) \
    asm volatile("cp.async.cg.shared.global [%0], [%1], 16;" :: "r"(DST), "l"(SRC))
#define CP_COMMIT() asm volatile("cp.async.commit_group;" ::: "memory")
#define CP_WAIT2()  asm volatile("cp.async.wait_group 2;" ::: "memory")

// swizzled smem offset: 64B rows (32 halves), 4x 16B chunks, chunk ^= (row>>1)&3
__device__ __forceinline__ uint32_t swoff(uint32_t row, uint32_t c) {
    return (row << 6) + (((c ^ ((row >> 1) & 3u)) & 3u) << 4);
}

__device__ __forceinline__ uint4 pack_half8(float4 a, float4 b) {
    uint4 r;
    __half2 h0 = __floats2half2_rn(a.x, a.y);
    __half2 h1 = __floats2half2_rn(a.z, a.w);
    __half2 h2 = __floats2half2_rn(b.x, b.y);
    __half2 h3 = __floats2half2_rn(b.z, b.w);
    r.x = *(uint32_t*)&h0; r.y = *(uint32_t*)&h1;
    r.z = *(uint32_t*)&h2; r.w = *(uint32_t*)&h3;
    return r;
}

// ---------------------------------------------------------------------------
// Fused preprocessing kernel (no tohalf): block-ID dispatch, 256 threads/block.
//  [0, 1024)       transpose Wa1[:C] -> g_wt1
//  [1024, 2048)    transpose Wa2     -> g_wt2
//  [2048, 2560)    transpose Wc1     -> g_wc1h
//  [2560, 2592)    embc
//  [2592]          bucket
// ---------------------------------------------------------------------------
#define OFF_T2   1024
#define OFF_WC1  2048
#define OFF_EMBC 2560
#define OFF_BUCK 2592
#define PREP_GRID (OFF_BUCK + 1)

__global__ __launch_bounds__(256) void prep_kernel(
    const int* __restrict__ sidx,
    const float* __restrict__ emb,    const float* __restrict__ Wa1,
    const float* __restrict__ ba1,    const float* __restrict__ Wa2,
    const float* __restrict__ Wc1)
{
    __shared__ float pool[2112];
    const int b   = blockIdx.x;
    const int tid = threadIdx.x;

    if (b < OFF_WC1) {
        // ---- weight transpose (wt1 / wt2) ----
        const int bb = (b < OFF_T2) ? b : (b - OFF_T2);
        const float* in = (b < OFF_T2) ? Wa1 : Wa2;
        __half* out = (b < OFF_T2) ? g_wt1 : g_wt2;
        const int n0 = (bb & 31) * 32, k0 = (bb >> 5) * 32;
        const int x = tid & 31, y = tid >> 5;
        float (*tile)[33] = (float(*)[33])pool;
#pragma unroll
        for (int j = 0; j < 32; j += 8)
            tile[y + j][x] = in[(size_t)(k0 + y + j) * 1024 + n0 + x];
        __syncthreads();
#pragma unroll
        for (int j = 0; j < 32; j += 8)
            out[(size_t)(n0 + y + j) * 1024 + k0 + x] = __float2half_rn(tile[x][y + j]);
    } else if (b < OFF_EMBC) {
        // ---- Wc1 [s][k][d] -> g_wc1h [s][d][k] ----
        const int bb = b - OFF_WC1;
        const int d0 = (bb & 1) * 32, k0 = ((bb >> 1) & 31) * 32, s = bb >> 6;
        const float* ip = Wc1 + (size_t)s * C_N * DC_N;
        __half* op = g_wc1h + (size_t)s * DC_N * C_N;
        const int x = tid & 31, y = tid >> 5;
        float (*tile)[33] = (float(*)[33])pool;
#pragma unroll
        for (int j = 0; j < 32; j += 8)
            tile[y + j][x] = ip[(size_t)(k0 + y + j) * DC_N + d0 + x];
        __syncthreads();
#pragma unroll
        for (int j = 0; j < 32; j += 8)
            op[(size_t)(d0 + y + j) * C_N + k0 + x] = __float2half_rn(tile[x][y + j]);
    } else if (b < OFF_BUCK) {
        // ---- embc ----
        const int bb = b - OFF_EMBC;
        const int ln = tid & 31;
        const int kc = tid >> 5;
        const int n  = bb * 32 + ln;
        float acc[S_N];
#pragma unroll
        for (int s = 0; s < S_N; s++) acc[s] = 0.f;
        const float* wp = Wa1 + (size_t)(C_N + kc * 128) * H_N + n;
        const float* ep = emb + kc * 128;
        for (int k = 0; k < 128; k++) {
            float w = wp[(size_t)k * H_N];
#pragma unroll
            for (int s = 0; s < S_N; s++) acc[s] += ep[s * H_N + k] * w;
        }
#pragma unroll
        for (int s = 0; s < S_N; s++)
            pool[(kc * S_N + s) * 32 + ln] = acc[s];
        __syncthreads();
        if (kc == 0) {
            float bias = ba1[n];
#pragma unroll
            for (int s = 0; s < S_N; s++) {
                float v = bias;
#pragma unroll
                for (int c = 0; c < 8; c++) v += pool[(c * S_N + s) * 32 + ln];
                g_embc[s * H_N + n] = v;
            }
        }
    } else {
        // ---- bucket: 256 threads, 128 samples each, styles padded to x32 ----
        int* ip = (int*)pool;
        int* wtot  = ip;
        int* wbase = ip + 64;
        int* gbase = ip + 128;
        const int lane = tid & 31, warp = tid >> 5;

#pragma unroll
        for (int i = 0; i < 129; i++) g_perm[tid + i * 256] = -1;

        int cnt[S_N];
#pragma unroll
        for (int s = 0; s < S_N; s++) cnt[s] = 0;
        const int base = tid * 128;
        for (int i = 0; i < 128; i++) {
            int v = sidx[base + i];
#pragma unroll
            for (int s = 0; s < S_N; s++) cnt[s] += (v == s);
        }

        int pre[S_N];
#pragma unroll
        for (int s = 0; s < S_N; s++) {
            int x = cnt[s];
            int inc = x;
#pragma unroll
            for (int o = 1; o < 32; o <<= 1) {
                int y = __shfl_up_sync(0xffffffffu, inc, o);
                if (lane >= o) inc += y;
            }
            pre[s] = inc - x;
            if (lane == 31) wtot[warp * S_N + s] = inc;
        }
        __syncthreads();

        if (tid == 0) {
            int acc = 0;
#pragma unroll
            for (int s = 0; s < S_N; s++) {
                int run = 0;
#pragma unroll
                for (int w = 0; w < 8; w++) {
                    wbase[w * S_N + s] = run;
                    run += wtot[w * S_N + s];
                }
                gbase[s] = acc;
                acc += ((run + 31) / 32) * 32;
            }
        }
        __syncthreads();

        int pos[S_N];
#pragma unroll
        for (int s = 0; s < S_N; s++)
            pos[s] = gbase[s] + wbase[warp * S_N + s] + pre[s];
        for (int i = 0; i < 128; i++) {
            int idx = base + i;
            int v = sidx[idx];
#pragma unroll
            for (int s = 0; s < S_N; s++) {
                if (v == s) g_perm[pos[s]++] = idx;
            }
        }
    }
}

// ---------------------------------------------------------------------------
// GEMM1: g_hid = half(relu(logits(f32, inline cvt) @ wt1^T + emb_c[sidx]))
// A: f32 LDG register-prefetch -> cvt -> STS, 2-buffer ring.
// B: cp.async half, 4-buffer ring. One barrier per k-tile.
// ---------------------------------------------------------------------------
__global__ __launch_bounds__(256, 2) void gemm1_h_kernel(
    const float* __restrict__ logits, const __half* __restrict__ wt1,
    const int* __restrict__ sidx)
{
    __shared__ __align__(16) __half As[2][128 * 32];
    __shared__ __align__(16) __half Bs[4][128 * 32];

    const int tid  = threadIdx.x;
    const int lane = tid & 31;
    const int warp = tid >> 5;
    const int bm0  = blockIdx.y * 128;
    const int bn0  = blockIdx.x * 128;
    const int warpM = (warp & 3) * 32;
    const int warpN = (warp >> 2) * 64;

    const uint32_t Ab = smem_u32(As);
    const uint32_t Bb = smem_u32(Bs);

    const int ar0 = tid >> 2, ac0 = tid & 3;
    const int ar1 = (tid + 256) >> 2;
    const uint32_t stA0 = swoff(ar0, ac0), stA1 = swoff(ar1, ac0);
    const float*  aSrc0 = logits + (size_t)(bm0 + ar0) * 1024 + ac0 * 8;
    const float*  aSrc1 = logits + (size_t)(bm0 + ar1) * 1024 + ac0 * 8;
    const __half* bSrc0 = wt1 + (size_t)(bn0 + ar0) * 1024 + ac0 * 8;
    const __half* bSrc1 = wt1 + (size_t)(bn0 + ar1) * 1024 + ac0 * 8;

    const uint32_t rA0 = warpM + (lane & 15);
    const uint32_t rA1 = warpM + 16 + (lane & 15);
    const uint32_t hiA = (lane >> 4) & 1;
    const uint32_t rB  = warpN + (lane & 7) + ((lane >> 4) & 1) * 8;
    const uint32_t hiB = (lane >> 3) & 1;

    float acc[2][8][4];
#pragma unroll
    for (int mt = 0; mt < 2; mt++)
#pragma unroll
        for (int nt = 0; nt < 8; nt++)
#pragma unroll
            for (int q = 0; q < 4; q++) acc[mt][nt][q] = 0.f;

    // B prologue: tiles 0..2 via cp.async
#pragma unroll
    for (int p = 0; p < 3; p++) {
        CPA16(Bb + p * 8192 + stA0, bSrc0 + p * 32);
        CPA16(Bb + p * 8192 + stA1, bSrc1 + p * 32);
        CP_COMMIT();
    }
    // A tile 0 into registers
    float4 a00 = *(const float4*)(aSrc0);
    float4 a01 = *(const float4*)(aSrc0 + 4);
    float4 a10 = *(const float4*)(aSrc1);
    float4 a11 = *(const float4*)(aSrc1 + 4);

    for (int t = 0; t < 32; t++) {
        // STS A(t) (cvt f32->half)
        *(uint4*)((char*)As[t & 1] + stA0) = pack_half8(a00, a01);
        *(uint4*)((char*)As[t & 1] + stA1) = pack_half8(a10, a11);
        // prefetch A(t+1)
        if (t + 1 < 32) {
            int kt = (t + 1) * 32;
            a00 = *(const float4*)(aSrc0 + kt);
            a01 = *(const float4*)(aSrc0 + kt + 4);
            a10 = *(const float4*)(aSrc1 + kt);
            a11 = *(const float4*)(aSrc1 + kt + 4);
        }
        CP_WAIT2();
        __syncthreads();
        if (t + 3 < 32) {
            int kt = (t + 3) * 32;
            CPA16(Bb + ((t + 3) & 3) * 8192 + stA0, bSrc0 + kt);
            CPA16(Bb + ((t + 3) & 3) * 8192 + stA1, bSrc1 + kt);
            CP_COMMIT();
        }
        const uint32_t Abase = Ab + (t & 1) * 8192;
        const uint32_t Bbase = Bb + (t & 3) * 8192;
#pragma unroll
        for (int ks = 0; ks < 2; ks++) {
            uint32_t a0[4], a1[4], bfr[4][4];
            LDSM4(a0[0], a0[1], a0[2], a0[3], Abase + swoff(rA0, 2 * ks + hiA));
            LDSM4(a1[0], a1[1], a1[2], a1[3], Abase + swoff(rA1, 2 * ks + hiA));
#pragma unroll
            for (int j = 0; j < 4; j++)
                LDSM4(bfr[j][0], bfr[j][1], bfr[j][2], bfr[j][3],
                      Bbase + swoff(rB + j * 16, 2 * ks + hiB));
#pragma unroll
            for (int j = 0; j < 4; j++) {
                MMA16816(acc[0][2 * j],     a0, bfr[j][0], bfr[j][1]);
                MMA16816(acc[0][2 * j + 1], a0, bfr[j][2], bfr[j][3]);
                MMA16816(acc[1][2 * j],     a1, bfr[j][0], bfr[j][1]);
                MMA16816(acc[1][2 * j + 1], a1, bfr[j][2], bfr[j][3]);
            }
        }
    }

    // epilogue: relu(acc + emb_c[sidx]) -> half -> g_hid
    const int colb = 2 * (lane & 3);
    const int rowb = lane >> 2;
#pragma unroll
    for (int mt = 0; mt < 2; mt++) {
        int r = bm0 + warpM + mt * 16 + rowb;
        int s0 = sidx[r], s1 = sidx[r + 8];
        const float* e0p = g_embc + s0 * H_N;
        const float* e1p = g_embc + s1 * H_N;
#pragma unroll
        for (int nt = 0; nt < 8; nt++) {
            int col = bn0 + warpN + nt * 8 + colb;
            float2 e0 = *(const float2*)(e0p + col);
            float2 e1 = *(const float2*)(e1p + col);
            __half2 h0 = __floats2half2_rn(fmaxf(acc[mt][nt][0] + e0.x, 0.f),
                                           fmaxf(acc[mt][nt][1] + e0.y, 0.f));
            __half2 h1 = __floats2half2_rn(fmaxf(acc[mt][nt][2] + e1.x, 0.f),
                                           fmaxf(acc[mt][nt][3] + e1.y, 0.f));
            *(__half2*)(g_hid + (size_t)r * H_N + col)       = h0;
            *(__half2*)(g_hid + (size_t)(r + 8) * H_N + col) = h1;
        }
    }
}

// ---------------------------------------------------------------------------
// GEMM2: out = logits + g_hid @ wt2^T + ba2 (all-half A via cp.async, 4-stage)
// ---------------------------------------------------------------------------
__global__ __launch_bounds__(256, 2) void gemm2_h_kernel(
    const __half* __restrict__ wt2, const float* __restrict__ logits,
    const float* __restrict__ ba2, float* __restrict__ out)
{
    __shared__ __align__(16) __half As[4][128 * 32];
    __shared__ __align__(16) __half Bs[4][128 * 32];

    const int tid  = threadIdx.x;
    const int lane = tid & 31;
    const int warp = tid >> 5;
    const int bm0  = blockIdx.y * 128;
    const int bn0  = blockIdx.x * 128;
    const int warpM = (warp & 3) * 32;
    const int warpN = (warp >> 2) * 64;

    const uint32_t Ab = smem_u32(As);
    const uint32_t Bb = smem_u32(Bs);

    const int ar0 = tid >> 2, ac0 = tid & 3;
    const int ar1 = (tid + 256) >> 2;
    const uint32_t stA0 = swoff(ar0, ac0), stA1 = swoff(ar1, ac0);
    const __half* aSrc0 = g_hid + (size_t)(bm0 + ar0) * 1024 + ac0 * 8;
    const __half* aSrc1 = g_hid + (size_t)(bm0 + ar1) * 1024 + ac0 * 8;
    const __half* bSrc0 = wt2 + (size_t)(bn0 + ar0) * 1024 + ac0 * 8;
    const __half* bSrc1 = wt2 + (size_t)(bn0 + ar1) * 1024 + ac0 * 8;

    const uint32_t rA0 = warpM + (lane & 15);
    const uint32_t rA1 = warpM + 16 + (lane & 15);
    const uint32_t hiA = (lane >> 4) & 1;
    const uint32_t rB  = warpN + (lane & 7) + ((lane >> 4) & 1) * 8;
    const uint32_t hiB = (lane >> 3) & 1;

    float acc[2][8][4];
#pragma unroll
    for (int mt = 0; mt < 2; mt++)
#pragma unroll
        for (int nt = 0; nt < 8; nt++)
#pragma unroll
            for (int q = 0; q < 4; q++) acc[mt][nt][q] = 0.f;

#pragma unroll
    for (int p = 0; p < 3; p++) {
        CPA16(Ab + p * 8192 + stA0, aSrc0 + p * 32);
        CPA16(Ab + p * 8192 + stA1, aSrc1 + p * 32);
        CPA16(Bb + p * 8192 + stA0, bSrc0 + p * 32);
        CPA16(Bb + p * 8192 + stA1, bSrc1 + p * 32);
        CP_COMMIT();
    }

    for (int t = 0; t < 32; t++) {
        CP_WAIT2();
        __syncthreads();
        if (t + 3 < 32) {
            int kt = (t + 3) * 32;
            int bf = (t + 3) & 3;
            CPA16(Ab + bf * 8192 + stA0, aSrc0 + kt);
            CPA16(Ab + bf * 8192 + stA1, aSrc1 + kt);
            CPA16(Bb + bf * 8192 + stA0, bSrc0 + kt);
            CPA16(Bb + bf * 8192 + stA1, bSrc1 + kt);
            CP_COMMIT();
        }
        const uint32_t Abase = Ab + (t & 3) * 8192;
        const uint32_t Bbase = Bb + (t & 3) * 8192;
#pragma unroll
        for (int ks = 0; ks < 2; ks++) {
            uint32_t a0[4], a1[4], bfr[4][4];
            LDSM4(a0[0], a0[1], a0[2], a0[3], Abase + swoff(rA0, 2 * ks + hiA));
            LDSM4(a1[0], a1[1], a1[2], a1[3], Abase + swoff(rA1, 2 * ks + hiA));
#pragma unroll
            for (int j = 0; j < 4; j++)
                LDSM4(bfr[j][0], bfr[j][1], bfr[j][2], bfr[j][3],
                      Bbase + swoff(rB + j * 16, 2 * ks + hiB));
#pragma unroll
            for (int j = 0; j < 4; j++) {
                MMA16816(acc[0][2 * j],     a0, bfr[j][0], bfr[j][1]);
                MMA16816(acc[0][2 * j + 1], a0, bfr[j][2], bfr[j][3]);
                MMA16816(acc[1][2 * j],     a1, bfr[j][0], bfr[j][1]);
                MMA16816(acc[1][2 * j + 1], a1, bfr[j][2], bfr[j][3]);
            }
        }
    }

    const int colb = 2 * (lane & 3);
    const int rowb = lane >> 2;
#pragma unroll
    for (int mt = 0; mt < 2; mt++) {
        int r = bm0 + warpM + mt * 16 + rowb;
#pragma unroll
        for (int nt = 0; nt < 8; nt++) {
            int col = bn0 + warpN + nt * 8 + colb;
            float b0 = ba2[col], b1 = ba2[col + 1];
            float2 l0 = *(const float2*)(logits + (size_t)r * C_N + col);
            float2 l1 = *(const float2*)(logits + (size_t)(r + 8) * C_N + col);
            float2 o0, o1;
            o0.x = l0.x + acc[mt][nt][0] + b0;
            o0.y = l0.y + acc[mt][nt][1] + b1;
            o1.x = l1.x + acc[mt][nt][2] + b0;
            o1.y = l1.y + acc[mt][nt][3] + b1;
            *(float2*)(out + (size_t)r * C_N + col)       = o0;
            *(float2*)(out + (size_t)(r + 8) * C_N + col) = o1;
        }
    }
}

// ---------------------------------------------------------------------------
// Single-pass pipelined calibrator (32 rows/block, cp.async Wt 4-ring) — R13.
// ---------------------------------------------------------------------------
__global__ __launch_bounds__(256) void calib_kernel(
    const float* __restrict__ adj, const int* __restrict__ sidx,
    const __half* __restrict__ wc1h,
    const float* __restrict__ bc1, const float* __restrict__ Wc2,
    const float* __restrict__ bc2, float* __restrict__ conf)
{
    __shared__ int   rows[32];
    __shared__ float rowS[32];
    __shared__ __align__(16) __half Pt[2][32 * 72];
    __shared__ __align__(16) __half Wt[4][64 * 72];
    __shared__ float hacc[32];

    const int tid  = threadIdx.x;
    const int lane = tid & 31;
    const int warp = tid >> 5;
    const int base = blockIdx.x * 32;
    if (tid < 32) { rows[tid] = g_perm[base + tid]; hacc[tid] = 0.f; }
    __syncthreads();

    int s = -1;
    for (int i = 0; i < 32; i++) {
        if (rows[i] >= 0) { s = sidx[rows[i]]; break; }
    }
    if (s < 0) return;

    const int prow = tid >> 3, pk = (tid & 7) * 8;
    const int wrow = tid >> 2, wk = (tid & 3) * 16;
    const int   rr_p = rows[prow];
    const float* aRow = (rr_p >= 0) ? (adj + (size_t)rr_p * C_N) : adj;
    const __half* wsrc = wc1h + (size_t)s * DC_N * C_N + (size_t)wrow * C_N + wk;

    const uint32_t PtB = smem_u32(Pt), WtB = smem_u32(Wt);
    const uint32_t wdst = WtB + (uint32_t)wrow * 144 + (uint32_t)wk * 2;
    const int n0 = warp * 8;
    const int lane15 = lane & 15;
    const uint32_t aAddr0 = PtB + (uint32_t)(lane & 15) * 144 + ((lane >> 4) & 1) * 16;
    const uint32_t bAddr0 = WtB + (uint32_t)(n0 + (lane15 & 7)) * 144 + ((lane15 >> 3) & 1) * 16;

    const float L2E = 1.4426950408889634f;
    float acc2[2][4] = {{0.f, 0.f, 0.f, 0.f}, {0.f, 0.f, 0.f, 0.f}};
    float ssum = 0.f;

    float4 x0 = make_float4(0.f, 0.f, 0.f, 0.f), x1 = x0;
    if (rr_p >= 0) {
        x0 = *(const float4*)(aRow + pk);
        x1 = *(const float4*)(aRow + pk + 4);
    }
    CPA16(wdst,             wsrc);
    CPA16(wdst + 16,        wsrc + 8);
    CP_COMMIT();
    CPA16(wdst + 9216,      wsrc + 64);
    CPA16(wdst + 9216 + 16, wsrc + 64 + 8);
    CP_COMMIT();

    for (int t = 0; t < 16; t++) {
        const int pbuf = t & 1;
        const int wbuf = t & 3;
        float4 e0 = make_float4(0.f, 0.f, 0.f, 0.f), e1 = e0;
        if (rr_p >= 0) {
            e0.x = exp2f((x0.x - 4.f) * L2E); e0.y = exp2f((x0.y - 4.f) * L2E);
            e0.z = exp2f((x0.z - 4.f) * L2E); e0.w = exp2f((x0.w - 4.f) * L2E);
            e1.x = exp2f((x1.x - 4.f) * L2E); e1.y = exp2f((x1.y - 4.f) * L2E);
            e1.z = exp2f((x1.z - 4.f) * L2E); e1.w = exp2f((x1.w - 4.f) * L2E);
            ssum += (e0.x + e0.y) + (e0.z + e0.w) + (e1.x + e1.y) + (e1.z + e1.w);
        }
        *(uint4*)((char*)Pt[pbuf] + prow * 144 + pk * 2) = pack_half8(e0, e1);

        if (t + 1 < 16) {
            int kn = (t + 1) * 64;
            if (rr_p >= 0) {
                x0 = *(const float4*)(aRow + kn + pk);
                x1 = *(const float4*)(aRow + kn + pk + 4);
            }
        }
        if (t + 2 < 16) {
            int kn2 = (t + 2) * 64;
            uint32_t d2 = wdst + ((t + 2) & 3) * 9216;
            CPA16(d2,      wsrc + kn2);
            CPA16(d2 + 16, wsrc + kn2 + 8);
        }
        CP_COMMIT();
        CP_WAIT2();
        __syncthreads();

        const uint32_t aAddr = aAddr0 + pbuf * 4608;
        const uint32_t bAddr = bAddr0 + wbuf * 9216;
#pragma unroll
        for (int ks = 0; ks < 4; ks++) {
            uint32_t a0[4], a1[4], b0, b1;
            LDSM4(a0[0], a0[1], a0[2], a0[3], aAddr + ks * 32);
            LDSM4(a1[0], a1[1], a1[2], a1[3], aAddr + 16 * 144 + ks * 32);
            LDSM2(b0, b1, bAddr + ks * 32);
            MMA16816(acc2[0], a0, b0, b1);
            MMA16816(acc2[1], a1, b0, b1);
        }
    }

    ssum += __shfl_xor_sync(0xffffffffu, ssum, 1);
    ssum += __shfl_xor_sync(0xffffffffu, ssum, 2);
    ssum += __shfl_xor_sync(0xffffffffu, ssum, 4);
    if ((tid & 7) == 0) rowS[prow] = ssum;
    __syncthreads();

    {
        int c0 = n0 + (lane & 3) * 2;
        float b1a = bc1[s * DC_N + c0], b1b = bc1[s * DC_N + c0 + 1];
        float w2a = Wc2[s * DC_N + c0], w2b = Wc2[s * DC_N + c0 + 1];
#pragma unroll
        for (int mt = 0; mt < 2; mt++) {
            int ra = mt * 16 + (lane >> 2);
            float Sa = rowS[ra], Sb = rowS[ra + 8];
            float iSa = (Sa > 0.f) ? (1.f / Sa) : 0.f;
            float iSb = (Sb > 0.f) ? (1.f / Sb) : 0.f;
            float pa = fmaxf(acc2[mt][0] * iSa + b1a, 0.f) * w2a
                     + fmaxf(acc2[mt][1] * iSa + b1b, 0.f) * w2b;
            float pb = fmaxf(acc2[mt][2] * iSb + b1a, 0.f) * w2a
                     + fmaxf(acc2[mt][3] * iSb + b1b, 0.f) * w2b;
            pa += __shfl_xor_sync(0xffffffffu, pa, 1);
            pa += __shfl_xor_sync(0xffffffffu, pa, 2);
            pb += __shfl_xor_sync(0xffffffffu, pb, 1);
            pb += __shfl_xor_sync(0xffffffffu, pb, 2);
            if ((lane & 3) == 0) {
                atomicAdd(&hacc[ra], pa);
                atomicAdd(&hacc[ra + 8], pb);
            }
        }
    }
    __syncthreads();

    if (tid < 32 && rows[tid] >= 0)
        conf[rows[tid]] = 1.f / (1.f + expf(-(hacc[tid] + bc2[s])));
}

// ---------------------------------------------------------------------------
extern "C" void kernel_launch(void* const* d_in, const int* in_sizes, int n_in,
                              void* d_out, int out_size)
{
    const float* logits = (const float*)d_in[0];
    const int*   sidx   = (const int*)d_in[1];
    const float* semb   = (const float*)d_in[2];
    const float* Wa1    = (const float*)d_in[3];
    const float* ba1    = (const float*)d_in[4];
    const float* Wa2    = (const float*)d_in[5];
    const float* ba2    = (const float*)d_in[6];
    const float* Wc1    = (const float*)d_in[7];
    const float* bc1    = (const float*)d_in[8];
    const float* Wc2    = (const float*)d_in[9];
    const float* bc2    = (const float*)d_in[10];

    float* out  = (float*)d_out;
    float* conf = out + (size_t)B_N * C_N;

    __half* wt1;  cudaGetSymbolAddress((void**)&wt1, g_wt1);
    __half* wt2;  cudaGetSymbolAddress((void**)&wt2, g_wt2);
    __half* wc1h; cudaGetSymbolAddress((void**)&wc1h, g_wc1h);

    // fused preprocessing (no tohalf): transposes + embc + bucket
    prep_kernel<<<PREP_GRID, 256>>>(sidx, semb, Wa1, ba1, Wa2, Wc1);

    // adapter MLP
    gemm1_h_kernel<<<dim3(H_N / 128, B_N / 128), 256>>>(logits, wt1, sidx);
    gemm2_h_kernel<<<dim3(C_N / 128, B_N / 128), 256>>>(wt2, logits, ba2, out);

    // pipelined single-pass calibrator
    calib_kernel<<<PERM_N / 32, 256>>>(out, sidx, wc1h, bc1, Wc2, bc2, conf);
}

// round 16
// speedup vs baseline: 1.0195x; 1.0195x over previous
#include <cuda_runtime.h>
#include <cuda_fp16.h>
#include <math.h>
#include <stdint.h>

#define B_N 32768
#define C_N 1024
#define H_N 1024
#define S_N 8
#define DC_N 64
#define PERM_N (B_N + S_N * 32)   // 33024 = 256*129

// device-global scratch (allocation-free per harness rules)
__device__ __half g_logh[(size_t)B_N * C_N];    // logits as half (GEMM1 A + GEMM2 residual)
__device__ __half g_hid[(size_t)B_N * H_N];     // hidden (half) between GEMM1/GEMM2
__device__ __half g_wt1[(size_t)H_N * C_N];     // Wa1[:C,:]^T half  [n][k]
__device__ __half g_wt2[(size_t)C_N * H_N];     // Wa2^T half  [n][k]
__device__ __half g_wc1h[(size_t)S_N * DC_N * C_N]; // Wc1^T half [s][d][k]
__device__ float  g_embc[S_N * H_N];            // emb[s] @ Wa1[C:,:] + ba1
__device__ int    g_perm[PERM_N];

// ---------------------------------------------------------------------------
// helpers
// ---------------------------------------------------------------------------
__device__ __forceinline__ uint32_t smem_u32(const void* p) {
    uint32_t a;
    asm("{ .reg .u64 t; cvta.to.shared.u64 t, %1; cvt.u32.u64 %0, t; }" : "=r"(a) : "l"(p));
    return a;
}

#define LDSM4(R0, R1, R2, R3, ADDR) \
    asm volatile("ldmatrix.sync.aligned.m8n8.x4.shared.b16 {%0,%1,%2,%3}, [%4];" \
                 : "=r"(R0), "=r"(R1), "=r"(R2), "=r"(R3) : "r"(ADDR))

#define LDSM2(R0, R1, ADDR) \
    asm volatile("ldmatrix.sync.aligned.m8n8.x2.shared.b16 {%0,%1}, [%2];" \
                 : "=r"(R0), "=r"(R1) : "r"(ADDR))

#define MMA16816(C, A, B0, B1) \
    asm volatile("mma.sync.aligned.m16n8k16.row.col.f32.f16.f16.f32 " \
                 "{%0,%1,%2,%3},{%4,%5,%6,%7},{%8,%9},{%0,%1,%2,%3};" \
                 : "+f"((C)[0]), "+f"((C)[1]), "+f"((C)[2]), "+f"((C)[3]) \
                 : "r"((A)[0]), "r"((A)[1]), "r"((A)[2]), "r"((A)[3]), \
                   "r"(B0), "r"(B1))

#define CPA16(DST, SRC) \
    asm volatile("cp.async.cg.shared.global [%0], [%1], 16;" :: "r"(DST), "l"(SRC))
#define CP_COMMIT() asm volatile("cp.async.commit_group;" ::: "memory")
#define CP_WAIT2()  asm volatile("cp.async.wait_group 2;" ::: "memory")

// swizzled smem offset: 64B rows (32 halves), 4x 16B chunks, chunk ^= (row>>1)&3
__device__ __forceinline__ uint32_t swoff(uint32_t row, uint32_t c) {
    return (row << 6) + (((c ^ ((row >> 1) & 3u)) & 3u) << 4);
}

__device__ __forceinline__ uint4 pack_half8(float4 a, float4 b) {
    uint4 r;
    __half2 h0 = __floats2half2_rn(a.x, a.y);
    __half2 h1 = __floats2half2_rn(a.z, a.w);
    __half2 h2 = __floats2half2_rn(b.x, b.y);
    __half2 h3 = __floats2half2_rn(b.z, b.w);
    r.x = *(uint32_t*)&h0; r.y = *(uint32_t*)&h1;
    r.z = *(uint32_t*)&h2; r.w = *(uint32_t*)&h3;
    return r;
}

// ---------------------------------------------------------------------------
// Fused preprocessing kernel: block-ID dispatch, 256 threads/block.
//  [0, 16384)          tohalf: logits -> g_logh
//  [16384, 17408)      transpose Wa1[:C]   -> g_wt1
//  [17408, 18432)      transpose Wa2       -> g_wt2
//  [18432, 18944)      transpose Wc1       -> g_wc1h
//  [18944, 18976)      embc
//  [18976]             bucket
// ---------------------------------------------------------------------------
#define OFF_T1   16384
#define OFF_T2   (OFF_T1 + 1024)
#define OFF_WC1  (OFF_T2 + 1024)
#define OFF_EMBC (OFF_WC1 + 512)
#define OFF_BUCK (OFF_EMBC + 32)
#define PREP_GRID (OFF_BUCK + 1)

__global__ __launch_bounds__(256) void prep_kernel(
    const float* __restrict__ logits, const int* __restrict__ sidx,
    const float* __restrict__ emb,    const float* __restrict__ Wa1,
    const float* __restrict__ ba1,    const float* __restrict__ Wa2,
    const float* __restrict__ Wc1)
{
    __shared__ float pool[2112];
    const int b   = blockIdx.x;
    const int tid = threadIdx.x;

    if (b < OFF_T1) {
        // ---- tohalf ----
        size_t i = ((size_t)b * 256 + tid) * 8;
        float4 a = *(const float4*)(logits + i);
        float4 c = *(const float4*)(logits + i + 4);
        *(uint4*)(g_logh + i) = pack_half8(a, c);
    } else if (b < OFF_WC1) {
        // ---- weight transpose (wt1 / wt2) ----
        const int bb = (b < OFF_T2) ? (b - OFF_T1) : (b - OFF_T2);
        const float* in = (b < OFF_T2) ? Wa1 : Wa2;
        __half* out = (b < OFF_T2) ? g_wt1 : g_wt2;
        const int n0 = (bb & 31) * 32, k0 = (bb >> 5) * 32;
        const int x = tid & 31, y = tid >> 5;
        float (*tile)[33] = (float(*)[33])pool;
#pragma unroll
        for (int j = 0; j < 32; j += 8)
            tile[y + j][x] = in[(size_t)(k0 + y + j) * 1024 + n0 + x];
        __syncthreads();
#pragma unroll
        for (int j = 0; j < 32; j += 8)
            out[(size_t)(n0 + y + j) * 1024 + k0 + x] = __float2half_rn(tile[x][y + j]);
    } else if (b < OFF_EMBC) {
        // ---- Wc1 [s][k][d] -> g_wc1h [s][d][k] ----
        const int bb = b - OFF_WC1;
        const int d0 = (bb & 1) * 32, k0 = ((bb >> 1) & 31) * 32, s = bb >> 6;
        const float* ip = Wc1 + (size_t)s * C_N * DC_N;
        __half* op = g_wc1h + (size_t)s * DC_N * C_N;
        const int x = tid & 31, y = tid >> 5;
        float (*tile)[33] = (float(*)[33])pool;
#pragma unroll
        for (int j = 0; j < 32; j += 8)
            tile[y + j][x] = ip[(size_t)(k0 + y + j) * DC_N + d0 + x];
        __syncthreads();
#pragma unroll
        for (int j = 0; j < 32; j += 8)
            op[(size_t)(d0 + y + j) * C_N + k0 + x] = __float2half_rn(tile[x][y + j]);
    } else if (b < OFF_BUCK) {
        // ---- embc ----
        const int bb = b - OFF_EMBC;
        const int ln = tid & 31;
        const int kc = tid >> 5;
        const int n  = bb * 32 + ln;
        float acc[S_N];
#pragma unroll
        for (int s = 0; s < S_N; s++) acc[s] = 0.f;
        const float* wp = Wa1 + (size_t)(C_N + kc * 128) * H_N + n;
        const float* ep = emb + kc * 128;
        for (int k = 0; k < 128; k++) {
            float w = wp[(size_t)k * H_N];
#pragma unroll
            for (int s = 0; s < S_N; s++) acc[s] += ep[s * H_N + k] * w;
        }
#pragma unroll
        for (int s = 0; s < S_N; s++)
            pool[(kc * S_N + s) * 32 + ln] = acc[s];
        __syncthreads();
        if (kc == 0) {
            float bias = ba1[n];
#pragma unroll
            for (int s = 0; s < S_N; s++) {
                float v = bias;
#pragma unroll
                for (int c = 0; c < 8; c++) v += pool[(c * S_N + s) * 32 + ln];
                g_embc[s * H_N + n] = v;
            }
        }
    } else {
        // ---- bucket: 256 threads, 128 samples each, styles padded to x32 ----
        int* ip = (int*)pool;
        int* wtot  = ip;
        int* wbase = ip + 64;
        int* gbase = ip + 128;
        const int lane = tid & 31, warp = tid >> 5;

#pragma unroll
        for (int i = 0; i < 129; i++) g_perm[tid + i * 256] = -1;

        int cnt[S_N];
#pragma unroll
        for (int s = 0; s < S_N; s++) cnt[s] = 0;
        const int base = tid * 128;
        for (int i = 0; i < 128; i++) {
            int v = sidx[base + i];
#pragma unroll
            for (int s = 0; s < S_N; s++) cnt[s] += (v == s);
        }

        int pre[S_N];
#pragma unroll
        for (int s = 0; s < S_N; s++) {
            int x = cnt[s];
            int inc = x;
#pragma unroll
            for (int o = 1; o < 32; o <<= 1) {
                int y = __shfl_up_sync(0xffffffffu, inc, o);
                if (lane >= o) inc += y;
            }
            pre[s] = inc - x;
            if (lane == 31) wtot[warp * S_N + s] = inc;
        }
        __syncthreads();

        if (tid == 0) {
            int acc = 0;
#pragma unroll
            for (int s = 0; s < S_N; s++) {
                int run = 0;
#pragma unroll
                for (int w = 0; w < 8; w++) {
                    wbase[w * S_N + s] = run;
                    run += wtot[w * S_N + s];
                }
                gbase[s] = acc;
                acc += ((run + 31) / 32) * 32;
            }
        }
        __syncthreads();

        int pos[S_N];
#pragma unroll
        for (int s = 0; s < S_N; s++)
            pos[s] = gbase[s] + wbase[warp * S_N + s] + pre[s];
        for (int i = 0; i < 128; i++) {
            int idx = base + i;
            int v = sidx[idx];
#pragma unroll
            for (int s = 0; s < S_N; s++) {
                if (v == s) g_perm[pos[s]++] = idx;
            }
        }
    }
}

// ---------------------------------------------------------------------------
// GEMM core: 128x128 tile, K=1024, fp16 HMMA + ldmatrix, cp.async 4-stage, occ2
// ---------------------------------------------------------------------------
#define GEMM_PROLOG(APTR, BPTR) \
    __shared__ __align__(16) __half As[4][128 * 32]; \
    __shared__ __align__(16) __half Bs[4][128 * 32]; \
    const int tid  = threadIdx.x; \
    const int lane = tid & 31; \
    const int warp = tid >> 5; \
    const int bm0  = blockIdx.y * 128; \
    const int bn0  = blockIdx.x * 128; \
    const int warpM = (warp & 3) * 32; \
    const int warpN = (warp >> 2) * 64; \
    const uint32_t Ab = smem_u32(As); \
    const uint32_t Bb = smem_u32(Bs); \
    const int ar0 = tid >> 2, ac0 = tid & 3; \
    const int ar1 = (tid + 256) >> 2, ac1 = ac0; \
    const uint32_t stA0 = swoff(ar0, ac0), stA1 = swoff(ar1, ac1); \
    const __half* aSrc0 = (APTR) + (size_t)(bm0 + ar0) * 1024 + ac0 * 8; \
    const __half* aSrc1 = (APTR) + (size_t)(bm0 + ar1) * 1024 + ac1 * 8; \
    const __half* bSrc0 = (BPTR) + (size_t)(bn0 + ar0) * 1024 + ac0 * 8; \
    const __half* bSrc1 = (BPTR) + (size_t)(bn0 + ar1) * 1024 + ac1 * 8; \
    const uint32_t rA0 = warpM + (lane & 15); \
    const uint32_t rA1 = warpM + 16 + (lane & 15); \
    const uint32_t hiA = (lane >> 4) & 1; \
    const uint32_t rB  = warpN + (lane & 7) + ((lane >> 4) & 1) * 8; \
    const uint32_t hiB = (lane >> 3) & 1; \
    float acc[2][8][4]; \
    _Pragma("unroll") \
    for (int mt = 0; mt < 2; mt++) \
        _Pragma("unroll") \
        for (int nt = 0; nt < 8; nt++) \
            _Pragma("unroll") \
            for (int q = 0; q < 4; q++) acc[mt][nt][q] = 0.f;

#define GEMM_LOAD_TILE(T_IDX) do { \
    int _b = (T_IDX) & 3; \
    int _kt = (T_IDX) * 32; \
    CPA16(Ab + _b * 8192 + stA0, aSrc0 + _kt); \
    CPA16(Ab + _b * 8192 + stA1, aSrc1 + _kt); \
    CPA16(Bb + _b * 8192 + stA0, bSrc0 + _kt); \
    CPA16(Bb + _b * 8192 + stA1, bSrc1 + _kt); \
    CP_COMMIT(); \
} while (0)

#define GEMM_MAINLOOP() \
    GEMM_LOAD_TILE(0); \
    GEMM_LOAD_TILE(1); \
    GEMM_LOAD_TILE(2); \
    for (int t = 0; t < 32; t++) { \
        CP_WAIT2(); \
        __syncthreads(); \
        if (t + 3 < 32) GEMM_LOAD_TILE(t + 3); \
        const uint32_t Abase = Ab + (t & 3) * 8192; \
        const uint32_t Bbase = Bb + (t & 3) * 8192; \
        _Pragma("unroll") \
        for (int ks = 0; ks < 2; ks++) { \
            uint32_t a0[4], a1[4], bfr[4][4]; \
            LDSM4(a0[0], a0[1], a0[2], a0[3], Abase + swoff(rA0, 2 * ks + hiA)); \
            LDSM4(a1[0], a1[1], a1[2], a1[3], Abase + swoff(rA1, 2 * ks + hiA)); \
            _Pragma("unroll") \
            for (int j = 0; j < 4; j++) \
                LDSM4(bfr[j][0], bfr[j][1], bfr[j][2], bfr[j][3], \
                      Bbase + swoff(rB + j * 16, 2 * ks + hiB)); \
            _Pragma("unroll") \
            for (int j = 0; j < 4; j++) { \
                MMA16816(acc[0][2 * j],     a0, bfr[j][0], bfr[j][1]); \
                MMA16816(acc[0][2 * j + 1], a0, bfr[j][2], bfr[j][3]); \
                MMA16816(acc[1][2 * j],     a1, bfr[j][0], bfr[j][1]); \
                MMA16816(acc[1][2 * j + 1], a1, bfr[j][2], bfr[j][3]); \
            } \
        } \
    }

// GEMM1: g_hid = half(relu(g_logh @ wt1^T + emb_c[sidx]))
__global__ __launch_bounds__(256, 2) void gemm1_h_kernel(
    const __half* __restrict__ wt1, const int* __restrict__ sidx)
{
    GEMM_PROLOG(g_logh, wt1)
    GEMM_MAINLOOP()

    const int colb = 2 * (lane & 3);
    const int rowb = lane >> 2;
#pragma unroll
    for (int mt = 0; mt < 2; mt++) {
        int r = bm0 + warpM + mt * 16 + rowb;
        int s0 = sidx[r], s1 = sidx[r + 8];
        const float* e0p = g_embc + s0 * H_N;
        const float* e1p = g_embc + s1 * H_N;
#pragma unroll
        for (int nt = 0; nt < 8; nt++) {
            int col = bn0 + warpN + nt * 8 + colb;
            float2 e0 = *(const float2*)(e0p + col);
            float2 e1 = *(const float2*)(e1p + col);
            __half2 h0 = __floats2half2_rn(fmaxf(acc[mt][nt][0] + e0.x, 0.f),
                                           fmaxf(acc[mt][nt][1] + e0.y, 0.f));
            __half2 h1 = __floats2half2_rn(fmaxf(acc[mt][nt][2] + e1.x, 0.f),
                                           fmaxf(acc[mt][nt][3] + e1.y, 0.f));
            *(__half2*)(g_hid + (size_t)r * H_N + col)       = h0;
            *(__half2*)(g_hid + (size_t)(r + 8) * H_N + col) = h1;
        }
    }
}

// GEMM2: out = logh(residual, half) + g_hid @ wt2^T + ba2
__global__ __launch_bounds__(256, 2) void gemm2_h_kernel(
    const __half* __restrict__ wt2, const float* __restrict__ ba2,
    float* __restrict__ out)
{
    GEMM_PROLOG(g_hid, wt2)
    GEMM_MAINLOOP()

    const int colb = 2 * (lane & 3);
    const int rowb = lane >> 2;
#pragma unroll
    for (int mt = 0; mt < 2; mt++) {
        int r = bm0 + warpM + mt * 16 + rowb;
#pragma unroll
        for (int nt = 0; nt < 8; nt++) {
            int col = bn0 + warpN + nt * 8 + colb;
            float b0 = ba2[col], b1 = ba2[col + 1];
            float2 l0 = __half22float2(*(const __half2*)(g_logh + (size_t)r * C_N + col));
            float2 l1 = __half22float2(*(const __half2*)(g_logh + (size_t)(r + 8) * C_N + col));
            float2 o0, o1;
            o0.x = l0.x + acc[mt][nt][0] + b0;
            o0.y = l0.y + acc[mt][nt][1] + b1;
            o1.x = l1.x + acc[mt][nt][2] + b0;
            o1.y = l1.y + acc[mt][nt][3] + b1;
            *(float2*)(out + (size_t)r * C_N + col)       = o0;
            *(float2*)(out + (size_t)(r + 8) * C_N + col) = o1;
        }
    }
}

// ---------------------------------------------------------------------------
// Single-pass pipelined calibrator (32 rows/block, cp.async Wt 4-ring) — R13.
// ---------------------------------------------------------------------------
__global__ __launch_bounds__(256) void calib_kernel(
    const float* __restrict__ adj, const int* __restrict__ sidx,
    const __half* __restrict__ wc1h,
    const float* __restrict__ bc1, const float* __restrict__ Wc2,
    const float* __restrict__ bc2, float* __restrict__ conf)
{
    __shared__ int   rows[32];
    __shared__ float rowS[32];
    __shared__ __align__(16) __half Pt[2][32 * 72];
    __shared__ __align__(16) __half Wt[4][64 * 72];
    __shared__ float hacc[32];

    const int tid  = threadIdx.x;
    const int lane = tid & 31;
    const int warp = tid >> 5;
    const int base = blockIdx.x * 32;
    if (tid < 32) { rows[tid] = g_perm[base + tid]; hacc[tid] = 0.f; }
    __syncthreads();

    int s = -1;
    for (int i = 0; i < 32; i++) {
        if (rows[i] >= 0) { s = sidx[rows[i]]; break; }
    }
    if (s < 0) return;

    const int prow = tid >> 3, pk = (tid & 7) * 8;
    const int wrow = tid >> 2, wk = (tid & 3) * 16;
    const int   rr_p = rows[prow];
    const float* aRow = (rr_p >= 0) ? (adj + (size_t)rr_p * C_N) : adj;
    const __half* wsrc = wc1h + (size_t)s * DC_N * C_N + (size_t)wrow * C_N + wk;

    const uint32_t PtB = smem_u32(Pt), WtB = smem_u32(Wt);
    const uint32_t wdst = WtB + (uint32_t)wrow * 144 + (uint32_t)wk * 2;
    const int n0 = warp * 8;
    const int lane15 = lane & 15;
    const uint32_t aAddr0 = PtB + (uint32_t)(lane & 15) * 144 + ((lane >> 4) & 1) * 16;
    const uint32_t bAddr0 = WtB + (uint32_t)(n0 + (lane15 & 7)) * 144 + ((lane15 >> 3) & 1) * 16;

    const float L2E = 1.4426950408889634f;
    float acc2[2][4] = {{0.f, 0.f, 0.f, 0.f}, {0.f, 0.f, 0.f, 0.f}};
    float ssum = 0.f;

    float4 x0 = make_float4(0.f, 0.f, 0.f, 0.f), x1 = x0;
    if (rr_p >= 0) {
        x0 = *(const float4*)(aRow + pk);
        x1 = *(const float4*)(aRow + pk + 4);
    }
    CPA16(wdst,             wsrc);
    CPA16(wdst + 16,        wsrc + 8);
    CP_COMMIT();
    CPA16(wdst + 9216,      wsrc + 64);
    CPA16(wdst + 9216 + 16, wsrc + 64 + 8);
    CP_COMMIT();

    for (int t = 0; t < 16; t++) {
        const int pbuf = t & 1;
        const int wbuf = t & 3;
        float4 e0 = make_float4(0.f, 0.f, 0.f, 0.f), e1 = e0;
        if (rr_p >= 0) {
            e0.x = exp2f((x0.x - 4.f) * L2E); e0.y = exp2f((x0.y - 4.f) * L2E);
            e0.z = exp2f((x0.z - 4.f) * L2E); e0.w = exp2f((x0.w - 4.f) * L2E);
            e1.x = exp2f((x1.x - 4.f) * L2E); e1.y = exp2f((x1.y - 4.f) * L2E);
            e1.z = exp2f((x1.z - 4.f) * L2E); e1.w = exp2f((x1.w - 4.f) * L2E);
            ssum += (e0.x + e0.y) + (e0.z + e0.w) + (e1.x + e1.y) + (e1.z + e1.w);
        }
        *(uint4*)((char*)Pt[pbuf] + prow * 144 + pk * 2) = pack_half8(e0, e1);

        if (t + 1 < 16) {
            int kn = (t + 1) * 64;
            if (rr_p >= 0) {
                x0 = *(const float4*)(aRow + kn + pk);
                x1 = *(const float4*)(aRow + kn + pk + 4);
            }
        }
        if (t + 2 < 16) {
            int kn2 = (t + 2) * 64;
            uint32_t d2 = wdst + ((t + 2) & 3) * 9216;
            CPA16(d2,      wsrc + kn2);
            CPA16(d2 + 16, wsrc + kn2 + 8);
        }
        CP_COMMIT();
        CP_WAIT2();
        __syncthreads();

        const uint32_t aAddr = aAddr0 + pbuf * 4608;
        const uint32_t bAddr = bAddr0 + wbuf * 9216;
#pragma unroll
        for (int ks = 0; ks < 4; ks++) {
            uint32_t a0[4], a1[4], b0, b1;
            LDSM4(a0[0], a0[1], a0[2], a0[3], aAddr + ks * 32);
            LDSM4(a1[0], a1[1], a1[2], a1[3], aAddr + 16 * 144 + ks * 32);
            LDSM2(b0, b1, bAddr + ks * 32);
            MMA16816(acc2[0], a0, b0, b1);
            MMA16816(acc2[1], a1, b0, b1);
        }
    }

    ssum += __shfl_xor_sync(0xffffffffu, ssum, 1);
    ssum += __shfl_xor_sync(0xffffffffu, ssum, 2);
    ssum += __shfl_xor_sync(0xffffffffu, ssum, 4);
    if ((tid & 7) == 0) rowS[prow] = ssum;
    __syncthreads();

    {
        int c0 = n0 + (lane & 3) * 2;
        float b1a = bc1[s * DC_N + c0], b1b = bc1[s * DC_N + c0 + 1];
        float w2a = Wc2[s * DC_N + c0], w2b = Wc2[s * DC_N + c0 + 1];
#pragma unroll
        for (int mt = 0; mt < 2; mt++) {
            int ra = mt * 16 + (lane >> 2);
            float Sa = rowS[ra], Sb = rowS[ra + 8];
            float iSa = (Sa > 0.f) ? (1.f / Sa) : 0.f;
            float iSb = (Sb > 0.f) ? (1.f / Sb) : 0.f;
            float pa = fmaxf(acc2[mt][0] * iSa + b1a, 0.f) * w2a
                     + fmaxf(acc2[mt][1] * iSa + b1b, 0.f) * w2b;
            float pb = fmaxf(acc2[mt][2] * iSb + b1a, 0.f) * w2a
                     + fmaxf(acc2[mt][3] * iSb + b1b, 0.f) * w2b;
            pa += __shfl_xor_sync(0xffffffffu, pa, 1);
            pa += __shfl_xor_sync(0xffffffffu, pa, 2);
            pb += __shfl_xor_sync(0xffffffffu, pb, 1);
            pb += __shfl_xor_sync(0xffffffffu, pb, 2);
            if ((lane & 3) == 0) {
                atomicAdd(&hacc[ra], pa);
                atomicAdd(&hacc[ra + 8], pb);
            }
        }
    }
    __syncthreads();

    if (tid < 32 && rows[tid] >= 0)
        conf[rows[tid]] = 1.f / (1.f + expf(-(hacc[tid] + bc2[s])));
}

// ---------------------------------------------------------------------------
extern "C" void kernel_launch(void* const* d_in, const int* in_sizes, int n_in,
                              void* d_out, int out_size)
{
    const float* logits = (const float*)d_in[0];
    const int*   sidx   = (const int*)d_in[1];
    const float* semb   = (const float*)d_in[2];
    const float* Wa1    = (const float*)d_in[3];
    const float* ba1    = (const float*)d_in[4];
    const float* Wa2    = (const float*)d_in[5];
    const float* ba2    = (const float*)d_in[6];
    const float* Wc1    = (const float*)d_in[7];
    const float* bc1    = (const float*)d_in[8];
    const float* Wc2    = (const float*)d_in[9];
    const float* bc2    = (const float*)d_in[10];

    float* out  = (float*)d_out;
    float* conf = out + (size_t)B_N * C_N;

    __half* wt1;  cudaGetSymbolAddress((void**)&wt1, g_wt1);
    __half* wt2;  cudaGetSymbolAddress((void**)&wt2, g_wt2);
    __half* wc1h; cudaGetSymbolAddress((void**)&wc1h, g_wc1h);

    // fused preprocessing: tohalf + transposes + embc + bucket (one launch)
    prep_kernel<<<PREP_GRID, 256>>>(logits, sidx, semb, Wa1, ba1, Wa2, Wc1);

    // adapter MLP (fp16 HMMA + ldmatrix + 4-stage cp.async, occ=2)
    gemm1_h_kernel<<<dim3(H_N / 128, B_N / 128), 256>>>(wt1, sidx);
    gemm2_h_kernel<<<dim3(C_N / 128, B_N / 128), 256>>>(wt2, ba2, out);

    // pipelined single-pass calibrator (32 rows/block, cp.async Wt ring)
    calib_kernel<<<PERM_N / 32, 256>>>(out, sidx, wc1h, bc1, Wc2, bc2, conf);
}

// round 17
// speedup vs baseline: 1.0242x; 1.0046x over previous
#include <cuda_runtime.h>
#include <cuda_fp16.h>
#include <math.h>
#include <stdint.h>

#define B_N 32768
#define C_N 1024
#define H_N 1024
#define S_N 8
#define DC_N 64
#define PERM_N (B_N + S_N * 32)   // 33024 = 256*129

// device-global scratch (allocation-free per harness rules)
__device__ __half g_logh[(size_t)B_N * C_N];    // logits as half (GEMM1 A)
__device__ __half g_hid[(size_t)B_N * H_N];     // hidden (half) between GEMM1/GEMM2
__device__ __half g_wt1[(size_t)H_N * C_N];     // Wa1[:C,:]^T half  [n][k]
__device__ __half g_wt2[(size_t)C_N * H_N];     // Wa2^T half  [n][k]
__device__ __half g_wc1h[(size_t)S_N * DC_N * C_N]; // Wc1^T half [s][d][k]
__device__ float  g_embc[S_N * H_N];            // emb[s] @ Wa1[C:,:] + ba1
__device__ int    g_perm[PERM_N];

// ---------------------------------------------------------------------------
// helpers
// ---------------------------------------------------------------------------
__device__ __forceinline__ uint32_t smem_u32(const void* p) {
    uint32_t a;
    asm("{ .reg .u64 t; cvta.to.shared.u64 t, %1; cvt.u32.u64 %0, t; }" : "=r"(a) : "l"(p));
    return a;
}

#define LDSM4(R0, R1, R2, R3, ADDR) \
    asm volatile("ldmatrix.sync.aligned.m8n8.x4.shared.b16 {%0,%1,%2,%3}, [%4];" \
                 : "=r"(R0), "=r"(R1), "=r"(R2), "=r"(R3) : "r"(ADDR))

#define LDSM2(R0, R1, ADDR) \
    asm volatile("ldmatrix.sync.aligned.m8n8.x2.shared.b16 {%0,%1}, [%2];" \
                 : "=r"(R0), "=r"(R1) : "r"(ADDR))

#define MMA16816(C, A, B0, B1) \
    asm volatile("mma.sync.aligned.m16n8k16.row.col.f32.f16.f16.f32 " \
                 "{%0,%1,%2,%3},{%4,%5,%6,%7},{%8,%9},{%0,%1,%2,%3};" \
                 : "+f"((C)[0]), "+f"((C)[1]), "+f"((C)[2]), "+f"((C)[3]) \
                 : "r"((A)[0]), "r"((A)[1]), "r"((A)[2]), "r"((A)[3]), \
                   "r"(B0), "r"(B1))

#define CPA16(DST, SRC) \
    asm volatile("cp.async.cg.shared.global [%0], [%1], 16;" :: "r"(DST), "l"(SRC))
#define CP_COMMIT() asm volatile("cp.async.commit_group;" ::: "memory")
#define CP_WAIT1()  asm volatile("cp.async.wait_group 1;" ::: "memory")
#define CP_WAIT2()  asm volatile("cp.async.wait_group 2;" ::: "memory")

// swizzled smem offset: 64B rows (32 halves), 4x 16B chunks, chunk ^= (row>>1)&3
__device__ __forceinline__ uint32_t swoff(uint32_t row, uint32_t c) {
    return (row << 6) + (((c ^ ((row >> 1) & 3u)) & 3u) << 4);
}

__device__ __forceinline__ uint4 pack_half8(float4 a, float4 b) {
    uint4 r;
    __half2 h0 = __floats2half2_rn(a.x, a.y);
    __half2 h1 = __floats2half2_rn(a.z, a.w);
    __half2 h2 = __floats2half2_rn(b.x, b.y);
    __half2 h3 = __floats2half2_rn(b.z, b.w);
    r.x = *(uint32_t*)&h0; r.y = *(uint32_t*)&h1;
    r.z = *(uint32_t*)&h2; r.w = *(uint32_t*)&h3;
    return r;
}

// ---------------------------------------------------------------------------
// Fused preprocessing kernel: block-ID dispatch, 256 threads/block.
// ---------------------------------------------------------------------------
#define OFF_T1   16384
#define OFF_T2   (OFF_T1 + 1024)
#define OFF_WC1  (OFF_T2 + 1024)
#define OFF_EMBC (OFF_WC1 + 512)
#define OFF_BUCK (OFF_EMBC + 32)
#define PREP_GRID (OFF_BUCK + 1)

__global__ __launch_bounds__(256) void prep_kernel(
    const float* __restrict__ logits, const int* __restrict__ sidx,
    const float* __restrict__ emb,    const float* __restrict__ Wa1,
    const float* __restrict__ ba1,    const float* __restrict__ Wa2,
    const float* __restrict__ Wc1)
{
    __shared__ float pool[2112];
    const int b   = blockIdx.x;
    const int tid = threadIdx.x;

    if (b < OFF_T1) {
        // ---- tohalf ----
        size_t i = ((size_t)b * 256 + tid) * 8;
        float4 a = *(const float4*)(logits + i);
        float4 c = *(const float4*)(logits + i + 4);
        *(uint4*)(g_logh + i) = pack_half8(a, c);
    } else if (b < OFF_WC1) {
        // ---- weight transpose (wt1 / wt2) ----
        const int bb = (b < OFF_T2) ? (b - OFF_T1) : (b - OFF_T2);
        const float* in = (b < OFF_T2) ? Wa1 : Wa2;
        __half* out = (b < OFF_T2) ? g_wt1 : g_wt2;
        const int n0 = (bb & 31) * 32, k0 = (bb >> 5) * 32;
        const int x = tid & 31, y = tid >> 5;
        float (*tile)[33] = (float(*)[33])pool;
#pragma unroll
        for (int j = 0; j < 32; j += 8)
            tile[y + j][x] = in[(size_t)(k0 + y + j) * 1024 + n0 + x];
        __syncthreads();
#pragma unroll
        for (int j = 0; j < 32; j += 8)
            out[(size_t)(n0 + y + j) * 1024 + k0 + x] = __float2half_rn(tile[x][y + j]);
    } else if (b < OFF_EMBC) {
        // ---- Wc1 [s][k][d] -> g_wc1h [s][d][k] ----
        const int bb = b - OFF_WC1;
        const int d0 = (bb & 1) * 32, k0 = ((bb >> 1) & 31) * 32, s = bb >> 6;
        const float* ip = Wc1 + (size_t)s * C_N * DC_N;
        __half* op = g_wc1h + (size_t)s * DC_N * C_N;
        const int x = tid & 31, y = tid >> 5;
        float (*tile)[33] = (float(*)[33])pool;
#pragma unroll
        for (int j = 0; j < 32; j += 8)
            tile[y + j][x] = ip[(size_t)(k0 + y + j) * DC_N + d0 + x];
        __syncthreads();
#pragma unroll
        for (int j = 0; j < 32; j += 8)
            op[(size_t)(d0 + y + j) * C_N + k0 + x] = __float2half_rn(tile[x][y + j]);
    } else if (b < OFF_BUCK) {
        // ---- embc ----
        const int bb = b - OFF_EMBC;
        const int ln = tid & 31;
        const int kc = tid >> 5;
        const int n  = bb * 32 + ln;
        float acc[S_N];
#pragma unroll
        for (int s = 0; s < S_N; s++) acc[s] = 0.f;
        const float* wp = Wa1 + (size_t)(C_N + kc * 128) * H_N + n;
        const float* ep = emb + kc * 128;
        for (int k = 0; k < 128; k++) {
            float w = wp[(size_t)k * H_N];
#pragma unroll
            for (int s = 0; s < S_N; s++) acc[s] += ep[s * H_N + k] * w;
        }
#pragma unroll
        for (int s = 0; s < S_N; s++)
            pool[(kc * S_N + s) * 32 + ln] = acc[s];
        __syncthreads();
        if (kc == 0) {
            float bias = ba1[n];
#pragma unroll
            for (int s = 0; s < S_N; s++) {
                float v = bias;
#pragma unroll
                for (int c = 0; c < 8; c++) v += pool[(c * S_N + s) * 32 + ln];
                g_embc[s * H_N + n] = v;
            }
        }
    } else {
        // ---- bucket ----
        int* ip = (int*)pool;
        int* wtot  = ip;
        int* wbase = ip + 64;
        int* gbase = ip + 128;
        const int lane = tid & 31, warp = tid >> 5;

#pragma unroll
        for (int i = 0; i < 129; i++) g_perm[tid + i * 256] = -1;

        int cnt[S_N];
#pragma unroll
        for (int s = 0; s < S_N; s++) cnt[s] = 0;
        const int base = tid * 128;
        for (int i = 0; i < 128; i++) {
            int v = sidx[base + i];
#pragma unroll
            for (int s = 0; s < S_N; s++) cnt[s] += (v == s);
        }

        int pre[S_N];
#pragma unroll
        for (int s = 0; s < S_N; s++) {
            int x = cnt[s];
            int inc = x;
#pragma unroll
            for (int o = 1; o < 32; o <<= 1) {
                int y = __shfl_up_sync(0xffffffffu, inc, o);
                if (lane >= o) inc += y;
            }
            pre[s] = inc - x;
            if (lane == 31) wtot[warp * S_N + s] = inc;
        }
        __syncthreads();

        if (tid == 0) {
            int acc = 0;
#pragma unroll
            for (int s = 0; s < S_N; s++) {
                int run = 0;
#pragma unroll
                for (int w = 0; w < 8; w++) {
                    wbase[w * S_N + s] = run;
                    run += wtot[w * S_N + s];
                }
                gbase[s] = acc;
                acc += ((run + 31) / 32) * 32;
            }
        }
        __syncthreads();

        int pos[S_N];
#pragma unroll
        for (int s = 0; s < S_N; s++)
            pos[s] = gbase[s] + wbase[warp * S_N + s] + pre[s];
        for (int i = 0; i < 128; i++) {
            int idx = base + i;
            int v = sidx[idx];
#pragma unroll
            for (int s = 0; s < S_N; s++) {
                if (v == s) g_perm[pos[s]++] = idx;
            }
        }
    }
}

// ---------------------------------------------------------------------------
// GEMM core: 128x128 tile, K-tile 64 (16 tiles), fp16 HMMA + ldmatrix,
// cp.async 3-stage ring (96 KB smem), 2 CTAs/SM, ONE barrier per 64-wide tile.
// Each 64-k tile = two 32-k subtiles (8 KB each) in the 64B-row swizzle layout.
// ---------------------------------------------------------------------------
#define GEMM_PROLOG(APTR, BPTR) \
    __shared__ __align__(16) __half As[3][128 * 64]; \
    __shared__ __align__(16) __half Bs[3][128 * 64]; \
    const int tid  = threadIdx.x; \
    const int lane = tid & 31; \
    const int warp = tid >> 5; \
    const int bm0  = blockIdx.y * 128; \
    const int bn0  = blockIdx.x * 128; \
    const int warpM = (warp & 3) * 32; \
    const int warpN = (warp >> 2) * 64; \
    const uint32_t Ab = smem_u32(As); \
    const uint32_t Bb = smem_u32(Bs); \
    const int ar0 = tid >> 2, ac0 = tid & 3; \
    const int ar1 = (tid + 256) >> 2; \
    const uint32_t stA0 = swoff(ar0, ac0), stA1 = swoff(ar1, ac0); \
    const __half* aSrc0 = (APTR) + (size_t)(bm0 + ar0) * 1024 + ac0 * 8; \
    const __half* aSrc1 = (APTR) + (size_t)(bm0 + ar1) * 1024 + ac0 * 8; \
    const __half* bSrc0 = (BPTR) + (size_t)(bn0 + ar0) * 1024 + ac0 * 8; \
    const __half* bSrc1 = (BPTR) + (size_t)(bn0 + ar1) * 1024 + ac0 * 8; \
    const uint32_t rA0 = warpM + (lane & 15); \
    const uint32_t rA1 = warpM + 16 + (lane & 15); \
    const uint32_t hiA = (lane >> 4) & 1; \
    const uint32_t rB  = warpN + (lane & 7) + ((lane >> 4) & 1) * 8; \
    const uint32_t hiB = (lane >> 3) & 1; \
    float acc[2][8][4]; \
    _Pragma("unroll") \
    for (int mt = 0; mt < 2; mt++) \
        _Pragma("unroll") \
        for (int nt = 0; nt < 8; nt++) \
            _Pragma("unroll") \
            for (int q = 0; q < 4; q++) acc[mt][nt][q] = 0.f;

// load one 64-k tile (two 32-k subtiles) via cp.async, single commit
#define GEMM_LOAD_TILE64(T_IDX) do { \
    int _b = (T_IDX) % 3; \
    int _kt = (T_IDX) * 64; \
    uint32_t _ab = Ab + _b * 16384; \
    uint32_t _bb = Bb + _b * 16384; \
    CPA16(_ab + stA0,        aSrc0 + _kt); \
    CPA16(_ab + stA1,        aSrc1 + _kt); \
    CPA16(_ab + 8192 + stA0, aSrc0 + _kt + 32); \
    CPA16(_ab + 8192 + stA1, aSrc1 + _kt + 32); \
    CPA16(_bb + stA0,        bSrc0 + _kt); \
    CPA16(_bb + stA1,        bSrc1 + _kt); \
    CPA16(_bb + 8192 + stA0, bSrc0 + _kt + 32); \
    CPA16(_bb + 8192 + stA1, bSrc1 + _kt + 32); \
    CP_COMMIT(); \
} while (0)

#define GEMM_MAINLOOP() \
    GEMM_LOAD_TILE64(0); \
    GEMM_LOAD_TILE64(1); \
    for (int t = 0; t < 16; t++) { \
        CP_WAIT1(); \
        __syncthreads(); \
        if (t + 2 < 16) GEMM_LOAD_TILE64(t + 2); \
        const uint32_t Abase = Ab + (t % 3) * 16384; \
        const uint32_t Bbase = Bb + (t % 3) * 16384; \
        _Pragma("unroll") \
        for (int ks = 0; ks < 4; ks++) { \
            const uint32_t sub = (ks >> 1) * 8192; \
            const uint32_t cA = 2 * (ks & 1) + hiA; \
            const uint32_t cB = 2 * (ks & 1) + hiB; \
            uint32_t a0[4], a1[4], bfr[4][4]; \
            LDSM4(a0[0], a0[1], a0[2], a0[3], Abase + sub + swoff(rA0, cA)); \
            LDSM4(a1[0], a1[1], a1[2], a1[3], Abase + sub + swoff(rA1, cA)); \
            _Pragma("unroll") \
            for (int j = 0; j < 4; j++) \
                LDSM4(bfr[j][0], bfr[j][1], bfr[j][2], bfr[j][3], \
                      Bbase + sub + swoff(rB + j * 16, cB)); \
            _Pragma("unroll") \
            for (int j = 0; j < 4; j++) { \
                MMA16816(acc[0][2 * j],     a0, bfr[j][0], bfr[j][1]); \
                MMA16816(acc[0][2 * j + 1], a0, bfr[j][2], bfr[j][3]); \
                MMA16816(acc[1][2 * j],     a1, bfr[j][0], bfr[j][1]); \
                MMA16816(acc[1][2 * j + 1], a1, bfr[j][2], bfr[j][3]); \
            } \
        } \
    }

// GEMM1: g_hid = half(relu(g_logh @ wt1^T + emb_c[sidx]))
__global__ __launch_bounds__(256, 2) void gemm1_h_kernel(
    const __half* __restrict__ wt1, const int* __restrict__ sidx)
{
    GEMM_PROLOG(g_logh, wt1)
    GEMM_MAINLOOP()

    const int colb = 2 * (lane & 3);
    const int rowb = lane >> 2;
#pragma unroll
    for (int mt = 0; mt < 2; mt++) {
        int r = bm0 + warpM + mt * 16 + rowb;
        int s0 = sidx[r], s1 = sidx[r + 8];
        const float* e0p = g_embc + s0 * H_N;
        const float* e1p = g_embc + s1 * H_N;
#pragma unroll
        for (int nt = 0; nt < 8; nt++) {
            int col = bn0 + warpN + nt * 8 + colb;
            float2 e0 = *(const float2*)(e0p + col);
            float2 e1 = *(const float2*)(e1p + col);
            __half2 h0 = __floats2half2_rn(fmaxf(acc[mt][nt][0] + e0.x, 0.f),
                                           fmaxf(acc[mt][nt][1] + e0.y, 0.f));
            __half2 h1 = __floats2half2_rn(fmaxf(acc[mt][nt][2] + e1.x, 0.f),
                                           fmaxf(acc[mt][nt][3] + e1.y, 0.f));
            *(__half2*)(g_hid + (size_t)r * H_N + col)       = h0;
            *(__half2*)(g_hid + (size_t)(r + 8) * H_N + col) = h1;
        }
    }
}

// GEMM2: out = logits + g_hid @ wt2^T + ba2
__global__ __launch_bounds__(256, 2) void gemm2_h_kernel(
    const __half* __restrict__ wt2, const float* __restrict__ logits,
    const float* __restrict__ ba2, float* __restrict__ out)
{
    GEMM_PROLOG(g_hid, wt2)
    GEMM_MAINLOOP()

    const int colb = 2 * (lane & 3);
    const int rowb = lane >> 2;
#pragma unroll
    for (int mt = 0; mt < 2; mt++) {
        int r = bm0 + warpM + mt * 16 + rowb;
#pragma unroll
        for (int nt = 0; nt < 8; nt++) {
            int col = bn0 + warpN + nt * 8 + colb;
            float b0 = ba2[col], b1 = ba2[col + 1];
            float2 l0 = *(const float2*)(logits + (size_t)r * C_N + col);
            float2 l1 = *(const float2*)(logits + (size_t)(r + 8) * C_N + col);
            float2 o0, o1;
            o0.x = l0.x + acc[mt][nt][0] + b0;
            o0.y = l0.y + acc[mt][nt][1] + b1;
            o1.x = l1.x + acc[mt][nt][2] + b0;
            o1.y = l1.y + acc[mt][nt][3] + b1;
            *(float2*)(out + (size_t)r * C_N + col)       = o0;
            *(float2*)(out + (size_t)(r + 8) * C_N + col) = o1;
        }
    }
}

// ---------------------------------------------------------------------------
// Single-pass pipelined calibrator (32 rows/block, cp.async Wt 4-ring) — R13.
// ---------------------------------------------------------------------------
__global__ __launch_bounds__(256) void calib_kernel(
    const float* __restrict__ adj, const int* __restrict__ sidx,
    const __half* __restrict__ wc1h,
    const float* __restrict__ bc1, const float* __restrict__ Wc2,
    const float* __restrict__ bc2, float* __restrict__ conf)
{
    __shared__ int   rows[32];
    __shared__ float rowS[32];
    __shared__ __align__(16) __half Pt[2][32 * 72];
    __shared__ __align__(16) __half Wt[4][64 * 72];
    __shared__ float hacc[32];

    const int tid  = threadIdx.x;
    const int lane = tid & 31;
    const int warp = tid >> 5;
    const int base = blockIdx.x * 32;
    if (tid < 32) { rows[tid] = g_perm[base + tid]; hacc[tid] = 0.f; }
    __syncthreads();

    int s = -1;
    for (int i = 0; i < 32; i++) {
        if (rows[i] >= 0) { s = sidx[rows[i]]; break; }
    }
    if (s < 0) return;

    const int prow = tid >> 3, pk = (tid & 7) * 8;
    const int wrow = tid >> 2, wk = (tid & 3) * 16;
    const int   rr_p = rows[prow];
    const float* aRow = (rr_p >= 0) ? (adj + (size_t)rr_p * C_N) : adj;
    const __half* wsrc = wc1h + (size_t)s * DC_N * C_N + (size_t)wrow * C_N + wk;

    const uint32_t PtB = smem_u32(Pt), WtB = smem_u32(Wt);
    const uint32_t wdst = WtB + (uint32_t)wrow * 144 + (uint32_t)wk * 2;
    const int n0 = warp * 8;
    const int lane15 = lane & 15;
    const uint32_t aAddr0 = PtB + (uint32_t)(lane & 15) * 144 + ((lane >> 4) & 1) * 16;
    const uint32_t bAddr0 = WtB + (uint32_t)(n0 + (lane15 & 7)) * 144 + ((lane15 >> 3) & 1) * 16;

    const float L2E = 1.4426950408889634f;
    float acc2[2][4] = {{0.f, 0.f, 0.f, 0.f}, {0.f, 0.f, 0.f, 0.f}};
    float ssum = 0.f;

    float4 x0 = make_float4(0.f, 0.f, 0.f, 0.f), x1 = x0;
    if (rr_p >= 0) {
        x0 = *(const float4*)(aRow + pk);
        x1 = *(const float4*)(aRow + pk + 4);
    }
    CPA16(wdst,             wsrc);
    CPA16(wdst + 16,        wsrc + 8);
    CP_COMMIT();
    CPA16(wdst + 9216,      wsrc + 64);
    CPA16(wdst + 9216 + 16, wsrc + 64 + 8);
    CP_COMMIT();

    for (int t = 0; t < 16; t++) {
        const int pbuf = t & 1;
        const int wbuf = t & 3;
        float4 e0 = make_float4(0.f, 0.f, 0.f, 0.f), e1 = e0;
        if (rr_p >= 0) {
            e0.x = exp2f((x0.x - 4.f) * L2E); e0.y = exp2f((x0.y - 4.f) * L2E);
            e0.z = exp2f((x0.z - 4.f) * L2E); e0.w = exp2f((x0.w - 4.f) * L2E);
            e1.x = exp2f((x1.x - 4.f) * L2E); e1.y = exp2f((x1.y - 4.f) * L2E);
            e1.z = exp2f((x1.z - 4.f) * L2E); e1.w = exp2f((x1.w - 4.f) * L2E);
            ssum += (e0.x + e0.y) + (e0.z + e0.w) + (e1.x + e1.y) + (e1.z + e1.w);
        }
        *(uint4*)((char*)Pt[pbuf] + prow * 144 + pk * 2) = pack_half8(e0, e1);

        if (t + 1 < 16) {
            int kn = (t + 1) * 64;
            if (rr_p >= 0) {
                x0 = *(const float4*)(aRow + kn + pk);
                x1 = *(const float4*)(aRow + kn + pk + 4);
            }
        }
        if (t + 2 < 16) {
            int kn2 = (t + 2) * 64;
            uint32_t d2 = wdst + ((t + 2) & 3) * 9216;
            CPA16(d2,      wsrc + kn2);
            CPA16(d2 + 16, wsrc + kn2 + 8);
        }
        CP_COMMIT();
        CP_WAIT2();
        __syncthreads();

        const uint32_t aAddr = aAddr0 + pbuf * 4608;
        const uint32_t bAddr = bAddr0 + wbuf * 9216;
#pragma unroll
        for (int ks = 0; ks < 4; ks++) {
            uint32_t a0[4], a1[4], b0, b1;
            LDSM4(a0[0], a0[1], a0[2], a0[3], aAddr + ks * 32);
            LDSM4(a1[0], a1[1], a1[2], a1[3], aAddr + 16 * 144 + ks * 32);
            LDSM2(b0, b1, bAddr + ks * 32);
            MMA16816(acc2[0], a0, b0, b1);
            MMA16816(acc2[1], a1, b0, b1);
        }
    }

    ssum += __shfl_xor_sync(0xffffffffu, ssum, 1);
    ssum += __shfl_xor_sync(0xffffffffu, ssum, 2);
    ssum += __shfl_xor_sync(0xffffffffu, ssum, 4);
    if ((tid & 7) == 0) rowS[prow] = ssum;
    __syncthreads();

    {
        int c0 = n0 + (lane & 3) * 2;
        float b1a = bc1[s * DC_N + c0], b1b = bc1[s * DC_N + c0 + 1];
        float w2a = Wc2[s * DC_N + c0], w2b = Wc2[s * DC_N + c0 + 1];
#pragma unroll
        for (int mt = 0; mt < 2; mt++) {
            int ra = mt * 16 + (lane >> 2);
            float Sa = rowS[ra], Sb = rowS[ra + 8];
            float iSa = (Sa > 0.f) ? (1.f / Sa) : 0.f;
            float iSb = (Sb > 0.f) ? (1.f / Sb) : 0.f;
            float pa = fmaxf(acc2[mt][0] * iSa + b1a, 0.f) * w2a
                     + fmaxf(acc2[mt][1] * iSa + b1b, 0.f) * w2b;
            float pb = fmaxf(acc2[mt][2] * iSb + b1a, 0.f) * w2a
                     + fmaxf(acc2[mt][3] * iSb + b1b, 0.f) * w2b;
            pa += __shfl_xor_sync(0xffffffffu, pa, 1);
            pa += __shfl_xor_sync(0xffffffffu, pa, 2);
            pb += __shfl_xor_sync(0xffffffffu, pb, 1);
            pb += __shfl_xor_sync(0xffffffffu, pb, 2);
            if ((lane & 3) == 0) {
                atomicAdd(&hacc[ra], pa);
                atomicAdd(&hacc[ra + 8], pb);
            }
        }
    }
    __syncthreads();

    if (tid < 32 && rows[tid] >= 0)
        conf[rows[tid]] = 1.f / (1.f + expf(-(hacc[tid] + bc2[s])));
}

// ---------------------------------------------------------------------------
extern "C" void kernel_launch(void* const* d_in, const int* in_sizes, int n_in,
                              void* d_out, int out_size)
{
    const float* logits = (const float*)d_in[0];
    const int*   sidx   = (const int*)d_in[1];
    const float* semb   = (const float*)d_in[2];
    const float* Wa1    = (const float*)d_in[3];
    const float* ba1    = (const float*)d_in[4];
    const float* Wa2    = (const float*)d_in[5];
    const float* ba2    = (const float*)d_in[6];
    const float* Wc1    = (const float*)d_in[7];
    const float* bc1    = (const float*)d_in[8];
    const float* Wc2    = (const float*)d_in[9];
    const float* bc2    = (const float*)d_in[10];

    float* out  = (float*)d_out;
    float* conf = out + (size_t)B_N * C_N;

    __half* wt1;  cudaGetSymbolAddress((void**)&wt1, g_wt1);
    __half* wt2;  cudaGetSymbolAddress((void**)&wt2, g_wt2);
    __half* wc1h; cudaGetSymbolAddress((void**)&wc1h, g_wc1h);

    // fused preprocessing: tohalf + transposes + embc + bucket (one launch)
    prep_kernel<<<PREP_GRID, 256>>>(logits, sidx, semb, Wa1, ba1, Wa2, Wc1);

    // adapter MLP (fp16 HMMA + ldmatrix, K-tile 64, 3-stage cp.async, occ=2)
    gemm1_h_kernel<<<dim3(H_N / 128, B_N / 128), 256>>>(wt1, sidx);
    gemm2_h_kernel<<<dim3(C_N / 128, B_N / 128), 256>>>(wt2, logits, ba2, out);

    // pipelined single-pass calibrator (32 rows/block, cp.async Wt ring)
    calib_kernel<<<PERM_N / 32, 256>>>(out, sidx, wc1h, bc1, Wc2, bc2, conf);
}